// round 4
// baseline (speedup 1.0000x reference)
#include <cuda_runtime.h>

// Problem constants
#define Sv   4096
#define Nv   262144
#define Ev   128
#define Hv   8
#define Dv   16
#define CKVv 64
#define QKD  512      // Hv * CKVv

// Device scratch
__device__ __align__(16) float g_Weff[2 * Ev * CKVv];  // folded Wkv: [256][64] (K rows 0..127, V rows 128..255)
__device__ __align__(16) float g_qk[Sv * QKD];         // per-segment folded query [S][8][64] (scale folded in)
__device__ __align__(16) float g_A[Sv * QKD];          // per-segment weighted x sums [S][8][64]
__device__ __align__(16) float g_den[Sv * Hv];
__device__ __align__(16) int g_cnt[Sv];
__device__ __align__(16) int g_offs[Sv + 4];
__device__ __align__(16) int g_cursor[Sv];
__device__ int g_order[Nv];

// ---------------------------------------------------------------------------
// prep: fold Wkv (concat([x,x]) @ Wkv.T == x @ (Wkv[:,:64]+Wkv[:,64:]).T),
// zero histogram
// ---------------------------------------------------------------------------
__global__ void prep_kernel(const float* __restrict__ Wkv) {
    int tid = blockIdx.x * blockDim.x + threadIdx.x;
    int nt  = gridDim.x * blockDim.x;
    for (int i = tid; i < Sv; i += nt) g_cnt[i] = 0;
    for (int i = tid; i < 2 * Ev * CKVv; i += nt) {
        int j = i >> 6;
        int c = i & 63;
        g_Weff[i] = Wkv[(j << 7) + c] + Wkv[(j << 7) + 64 + c];
    }
}

// ---------------------------------------------------------------------------
// Counting sort: histogram -> shfl scan -> scatter
// ---------------------------------------------------------------------------
__global__ void hist_kernel(const int* __restrict__ assign) {
    int tid = blockIdx.x * blockDim.x + threadIdx.x;
    if (tid < Nv) atomicAdd(&g_cnt[assign[tid]], 1);
}

__global__ void scan_kernel() {   // 1 block, 1024 threads, 4 bins each
    __shared__ int wsum[32];
    int t = threadIdx.x, lane = t & 31, wid = t >> 5;
    int4 c = ((const int4*)g_cnt)[t];
    int sum = c.x + c.y + c.z + c.w;
    int v = sum;
    #pragma unroll
    for (int o = 1; o < 32; o <<= 1) {
        int u = __shfl_up_sync(0xffffffffu, v, o);
        if (lane >= o) v += u;
    }
    if (lane == 31) wsum[wid] = v;
    __syncthreads();
    if (wid == 0) {
        int w = wsum[lane];
        #pragma unroll
        for (int o = 1; o < 32; o <<= 1) {
            int u = __shfl_up_sync(0xffffffffu, w, o);
            if (lane >= o) w += u;
        }
        wsum[lane] = w;
    }
    __syncthreads();
    int base = (wid ? wsum[wid - 1] : 0) + v - sum;  // exclusive prefix for this thread's 4 bins
    int o0 = base, o1 = o0 + c.x, o2 = o1 + c.y, o3 = o2 + c.z;
    int4 ov = make_int4(o0, o1, o2, o3);
    ((int4*)g_offs)[t]   = ov;
    ((int4*)g_cursor)[t] = ov;
    if (t == 1023) g_offs[Sv] = o3 + c.w;
}

__global__ void scatter_kernel(const int* __restrict__ assign) {
    int tid = blockIdx.x * blockDim.x + threadIdx.x;
    if (tid < Nv) {
        int s = assign[tid];
        int pos = atomicAdd(&g_cursor[s], 1);
        g_order[pos] = tid;
    }
}

// ---------------------------------------------------------------------------
// Fused Q + qk: block keeps Wq (64KB) + Wk (32KB) in smem, loops segments.
// qk[s][h][c] = 0.25 * sum_d Q[s][h*16+d] * Wk_eff[h*16+d][c]
// ---------------------------------------------------------------------------
__global__ void __launch_bounds__(128)
qqk_kernel(const float* __restrict__ sp, const float* __restrict__ Wq) {
    extern __shared__ float dyn[];
    float* Wq_s = dyn;                 // [128][128] swizzled (16384 floats)
    float* Wk_s = dyn + Ev * Ev;       // [128][64]  swizzled (8192 floats)
    __shared__ float sps[Ev];
    __shared__ float Qs[Ev];

    int t = threadIdx.x;

    for (int idx = t; idx < Ev * Ev / 4; idx += 128) {
        int j = idx >> 5, i4 = idx & 31;
        float4 v = ((const float4*)Wq)[idx];
        *(float4*)&Wq_s[j * Ev + ((i4 ^ (j & 31)) << 2)] = v;
    }
    for (int idx = t; idx < Ev * CKVv / 4; idx += 128) {
        int r = idx >> 4, c4 = idx & 15;
        float4 v = ((const float4*)g_Weff)[idx];
        *(float4*)&Wk_s[r * CKVv + ((c4 ^ (r & 15)) << 2)] = v;
    }
    __syncthreads();

    int h = t >> 4, c4 = t & 15;
    for (int s = blockIdx.x; s < Sv; s += gridDim.x) {
        sps[t] = sp[(size_t)s * Ev + t];
        __syncthreads();
        float acc = 0.f;
        const float* wr = Wq_s + (size_t)t * Ev;
        #pragma unroll
        for (int i4 = 0; i4 < 32; ++i4) {
            int oc = i4 ^ (t & 31);                 // original column group
            float4 w = *(const float4*)&wr[i4 << 2];  // holds original col (i4 ^ (t&31))... see note
            // Load swizzled slot i4 -> it contains original column group (i4 ^ (t&31)).
            acc = fmaf(w.x, sps[oc * 4 + 0], acc);
            acc = fmaf(w.y, sps[oc * 4 + 1], acc);
            acc = fmaf(w.z, sps[oc * 4 + 2], acc);
            acc = fmaf(w.w, sps[oc * 4 + 3], acc);
        }
        Qs[t] = acc;
        __syncthreads();
        float4 a = make_float4(0.f, 0.f, 0.f, 0.f);
        #pragma unroll
        for (int d = 0; d < Dv; ++d) {
            int r = h * Dv + d;
            float q = Qs[r];
            float4 w = *(const float4*)&Wk_s[r * CKVv + ((c4 ^ (r & 15)) << 2)];
            a.x = fmaf(q, w.x, a.x);
            a.y = fmaf(q, w.y, a.y);
            a.z = fmaf(q, w.z, a.z);
            a.w = fmaf(q, w.w, a.w);
        }
        a.x *= 0.25f; a.y *= 0.25f; a.z *= 0.25f; a.w *= 0.25f;
        *(float4*)&g_qk[(size_t)s * QKD + h * CKVv + c4 * 4] = a;
        __syncthreads();
    }
}

// ---------------------------------------------------------------------------
// Segment kernel: one block (128 threads) per segment; chunk = 64 points.
// ---------------------------------------------------------------------------
__global__ void __launch_bounds__(128)
seg_kernel(const float* __restrict__ xin, float* __restrict__ attn_out) {
    __shared__ float x_s[64 * 64];     // swizzled rows, 16 KB
    __shared__ float qk_s[QKD];        // 2 KB
    __shared__ float w_s[Hv * 64];     // transposed [h][p], 2 KB
    __shared__ float ps_s[2 * 64];     // partial score sums

    int s = blockIdx.x, t = threadIdx.x;
    ((float4*)qk_s)[t] = ((const float4*)(g_qk + (size_t)s * QKD))[t];

    int start = g_offs[s], end = g_offs[s + 1];
    int h = t >> 4, c4 = t & 15;
    int p1 = t & 63;
    int hf = t >> 6;
    float4 A = make_float4(0.f, 0.f, 0.f, 0.f);
    float den = 0.f;
    __syncthreads();

    for (int base = start; base < end; base += 64) {
        int P = min(64, end - base);
        for (int idx = t; idx < P * 16; idx += 128) {
            int r = idx >> 4, cc = idx & 15;
            int p = g_order[base + r];
            float4 v = ((const float4*)xin)[(size_t)p * 16 + cc];
            *(float4*)&x_s[r * 64 + ((cc ^ (r & 15)) << 2)] = v;
        }
        __syncthreads();

        // phase 1: 4 heads per thread, all 128 threads active
        if (p1 < P) {
            float4 xr[16];             // xr[i] = original column group i
            int sw = p1 & 15;
            #pragma unroll
            for (int i = 0; i < 16; ++i)
                xr[i] = *(const float4*)&x_s[p1 * 64 + ((i ^ sw) << 2)];
            // note: slot (i^sw) holds original col ((i^sw)^sw) = i  -> xr[i] correct
            float psum = 0.f;
            #pragma unroll
            for (int hh = 0; hh < 4; ++hh) {
                int hd = hf * 4 + hh;
                const float4* qv = (const float4*)(qk_s + hd * CKVv);
                float sc = 0.f;
                #pragma unroll
                for (int i = 0; i < 16; ++i) {
                    float4 q = qv[i];
                    float4 x = xr[i];
                    sc = fmaf(q.x, x.x, sc);
                    sc = fmaf(q.y, x.y, sc);
                    sc = fmaf(q.z, x.z, sc);
                    sc = fmaf(q.w, x.w, sc);
                }
                psum += sc;
                w_s[hd * 64 + p1] = __expf(sc);
            }
            ps_s[hf * 64 + p1] = psum;
        }
        __syncthreads();

        if (t < P)
            attn_out[g_order[base + t]] = (ps_s[t] + ps_s[64 + t]) * 0.125f;

        // phase 2
        int Pm = P & ~3;
        for (int p = 0; p < Pm; p += 4) {
            float4 wv = *(const float4*)&w_s[h * 64 + p];
            {
                int r = p;
                float4 xv = *(const float4*)&x_s[r * 64 + ((c4 ^ (r & 15)) << 2)];
                A.x = fmaf(wv.x, xv.x, A.x); A.y = fmaf(wv.x, xv.y, A.y);
                A.z = fmaf(wv.x, xv.z, A.z); A.w = fmaf(wv.x, xv.w, A.w);
            }
            {
                int r = p + 1;
                float4 xv = *(const float4*)&x_s[r * 64 + ((c4 ^ (r & 15)) << 2)];
                A.x = fmaf(wv.y, xv.x, A.x); A.y = fmaf(wv.y, xv.y, A.y);
                A.z = fmaf(wv.y, xv.z, A.z); A.w = fmaf(wv.y, xv.w, A.w);
            }
            {
                int r = p + 2;
                float4 xv = *(const float4*)&x_s[r * 64 + ((c4 ^ (r & 15)) << 2)];
                A.x = fmaf(wv.z, xv.x, A.x); A.y = fmaf(wv.z, xv.y, A.y);
                A.z = fmaf(wv.z, xv.z, A.z); A.w = fmaf(wv.z, xv.w, A.w);
            }
            {
                int r = p + 3;
                float4 xv = *(const float4*)&x_s[r * 64 + ((c4 ^ (r & 15)) << 2)];
                A.x = fmaf(wv.w, xv.x, A.x); A.y = fmaf(wv.w, xv.y, A.y);
                A.z = fmaf(wv.w, xv.z, A.z); A.w = fmaf(wv.w, xv.w, A.w);
            }
            if (c4 == 0) den += wv.x + wv.y + wv.z + wv.w;
        }
        for (int r = Pm; r < P; ++r) {
            float w = w_s[h * 64 + r];
            float4 xv = *(const float4*)&x_s[r * 64 + ((c4 ^ (r & 15)) << 2)];
            A.x = fmaf(w, xv.x, A.x); A.y = fmaf(w, xv.y, A.y);
            A.z = fmaf(w, xv.z, A.z); A.w = fmaf(w, xv.w, A.w);
            if (c4 == 0) den += w;
        }
        __syncthreads();
    }

    *(float4*)&g_A[(size_t)s * QKD + h * CKVv + c4 * 4] = A;
    if (c4 == 0) g_den[s * Hv + h] = den;
}

// ---------------------------------------------------------------------------
// ln_kernel: ctx = (Wv_eff . A[h]) / den; residual + LayerNorm.
// ---------------------------------------------------------------------------
__global__ void __launch_bounds__(128)
ln_kernel(const float* __restrict__ sp, const float* __restrict__ lnw,
          const float* __restrict__ lnb, float* __restrict__ out) {
    extern __shared__ float Wv_s[];    // [128][64] swizzled, 32 KB
    __shared__ float As[QKD];
    __shared__ float den_sh[Hv];
    __shared__ float red_s[4];

    int t = threadIdx.x, lane = t & 31, warp = t >> 5;

    for (int idx = t; idx < Ev * CKVv / 4; idx += 128) {
        int r = idx >> 4, c4 = idx & 15;
        float4 v = ((const float4*)(g_Weff + Ev * CKVv))[idx];
        *(float4*)&Wv_s[r * CKVv + ((c4 ^ (r & 15)) << 2)] = v;
    }
    __syncthreads();

    int h = t >> 4;
    int swt = t & 15;
    for (int s = blockIdx.x; s < Sv; s += gridDim.x) {
        ((float4*)As)[t] = ((const float4*)(g_A + (size_t)s * QKD))[t];
        if (t < Hv) den_sh[t] = g_den[s * Hv + t];
        __syncthreads();

        float acc = 0.f;
        const float* ah = As + h * CKVv;
        #pragma unroll
        for (int i = 0; i < 16; ++i) {
            int oc = i ^ swt;   // slot i holds original col group (i ^ swt)
            float4 w = *(const float4*)&Wv_s[t * CKVv + (i << 2)];
            const float* a = ah + (oc << 2);
            acc = fmaf(w.x, a[0], acc);
            acc = fmaf(w.y, a[1], acc);
            acc = fmaf(w.z, a[2], acc);
            acc = fmaf(w.w, a[3], acc);
        }
        float dd  = den_sh[h];
        float ctx = dd > 0.f ? acc / dd : 0.f;
        float xval = sp[(size_t)s * Ev + t] + ctx;

        float v = xval;
        #pragma unroll
        for (int o = 16; o; o >>= 1) v += __shfl_xor_sync(0xffffffffu, v, o);
        if (lane == 0) red_s[warp] = v;
        __syncthreads();
        float mu = (red_s[0] + red_s[1] + red_s[2] + red_s[3]) * (1.f / Ev);
        float dv = xval - mu;
        float sq = dv * dv;
        #pragma unroll
        for (int o = 16; o; o >>= 1) sq += __shfl_xor_sync(0xffffffffu, sq, o);
        __syncthreads();
        if (lane == 0) red_s[warp] = sq;
        __syncthreads();
        float rstd = rsqrtf((red_s[0] + red_s[1] + red_s[2] + red_s[3]) * (1.f / Ev) + 1e-5f);
        out[(size_t)s * Ev + t] = dv * rstd * lnw[t] + lnb[t];
        __syncthreads();
    }
}

// ---------------------------------------------------------------------------
// Launch. Inputs: sp_feat, rawPoint_feat, point_assignments, Wq, Wkv, ln_w, ln_b
// Output: [updated_sp_feat (S*E) | attn_scores (N)] f32.
// ---------------------------------------------------------------------------
extern "C" void kernel_launch(void* const* d_in, const int* in_sizes, int n_in,
                              void* d_out, int out_size) {
    const float* sp     = (const float*)d_in[0];
    const float* xin    = (const float*)d_in[1];
    const int*   assign = (const int*)d_in[2];
    const float* Wq     = (const float*)d_in[3];
    const float* Wkv    = (const float*)d_in[4];
    const float* lnw    = (const float*)d_in[5];
    const float* lnb    = (const float*)d_in[6];
    float* out      = (float*)d_out;
    float* attn_out = out + (size_t)Sv * Ev;

    prep_kernel<<<148, 256>>>(Wkv);
    hist_kernel<<<Nv / 256, 256>>>(assign);
    scan_kernel<<<1, 1024>>>();
    scatter_kernel<<<Nv / 256, 256>>>(assign);

    int qqk_smem = (Ev * Ev + Ev * CKVv) * (int)sizeof(float);   // 96 KB
    cudaFuncSetAttribute(qqk_kernel, cudaFuncAttributeMaxDynamicSharedMemorySize, qqk_smem);
    qqk_kernel<<<256, 128, qqk_smem>>>(sp, Wq);

    seg_kernel<<<Sv, 128>>>(xin, attn_out);

    int ln_smem = Ev * CKVv * (int)sizeof(float);                // 32 KB
    cudaFuncSetAttribute(ln_kernel, cudaFuncAttributeMaxDynamicSharedMemorySize, ln_smem);
    ln_kernel<<<256, 128, ln_smem>>>(sp, lnw, lnb, out);
}

// round 5
// speedup vs baseline: 1.7773x; 1.7773x over previous
#include <cuda_runtime.h>

// Problem constants
#define Sv   4096
#define Nv   262144
#define Ev   128
#define Hv   8
#define Dv   16
#define CKVv 64
#define QKD  512      // Hv * CKVv

// Device scratch (zero-initialized at load; g_cnt invariant: always zero at
// kernel_launch entry — scan_kernel re-zeroes it after consuming).
__device__ __align__(16) float g_Wv[Ev * CKVv];   // folded V weights [128][64]
__device__ __align__(16) float g_qk[Sv * QKD];    // per-segment folded query [S][8][64]
__device__ __align__(16) int g_cnt[Sv];
__device__ __align__(16) int g_offs[Sv + 4];
__device__ __align__(16) int g_cursor[Sv];
__device__ int g_order[Nv];

// ---------------------------------------------------------------------------
// pre_kernel (launch 0): histogram + fused Q/qk precompute.
//   - grid-stride histogram of point_assignments (atomics on g_cnt)
//   - Wq (64KB) + folded Wk (32KB) staged in smem, swizzled
//   - loops segments: Q[s] = sp[s] @ Wq.T;  qk[s][h][c] = 0.25*sum_d Q*Wk
//   - block 0 folds Wv into g_Wv for seg_kernel's tail
// Swizzle convention: row r stores original float4-group c at slot (c ^ (r & M)).
// Reads iterate the ORIGINAL group index and address slot (i ^ (r & M)) so the
// slot varies per lane -> conflict-free.
// ---------------------------------------------------------------------------
__global__ void __launch_bounds__(128)
pre_kernel(const float* __restrict__ sp, const float* __restrict__ Wq,
           const float* __restrict__ Wkv, const int* __restrict__ assign) {
    extern __shared__ float dyn[];
    float* Wq_s = dyn;                 // [128][128] swizzled
    float* Wk_s = dyn + Ev * Ev;       // [128][64]  swizzled (folded K)
    __shared__ float sps[Ev];
    __shared__ float Qs[Ev];

    int t = threadIdx.x;
    int gtid = blockIdx.x * 128 + t;

    // histogram
    for (int p = gtid; p < Nv; p += 256 * 128)
        atomicAdd(&g_cnt[assign[p]], 1);

    // stage Wq swizzled
    for (int idx = t; idx < Ev * Ev / 4; idx += 128) {
        int j = idx >> 5, i4 = idx & 31;
        float4 v = ((const float4*)Wq)[idx];
        *(float4*)&Wq_s[j * Ev + ((i4 ^ (j & 31)) << 2)] = v;
    }
    // fold + stage Wk (Wkv rows 0..127; concat-duplication fold)
    for (int idx = t; idx < Ev * CKVv / 4; idx += 128) {
        int r = idx >> 4, c4 = idx & 15;
        float4 a = *(const float4*)&Wkv[(size_t)r * 128 + c4 * 4];
        float4 b = *(const float4*)&Wkv[(size_t)r * 128 + 64 + c4 * 4];
        float4 v = make_float4(a.x + b.x, a.y + b.y, a.z + b.z, a.w + b.w);
        *(float4*)&Wk_s[r * CKVv + ((c4 ^ (r & 15)) << 2)] = v;
    }
    // block 0: fold Wv (Wkv rows 128..255) to global for seg's tail
    if (blockIdx.x == 0) {
        for (int idx = t; idx < Ev * CKVv / 4; idx += 128) {
            int r = idx >> 4, c4 = idx & 15;
            float4 a = *(const float4*)&Wkv[(size_t)(128 + r) * 128 + c4 * 4];
            float4 b = *(const float4*)&Wkv[(size_t)(128 + r) * 128 + 64 + c4 * 4];
            ((float4*)g_Wv)[idx] = make_float4(a.x + b.x, a.y + b.y, a.z + b.z, a.w + b.w);
        }
    }
    __syncthreads();

    int h = t >> 4, c4 = t & 15;
    int tw = t & 31;
    for (int s = blockIdx.x; s < Sv; s += gridDim.x) {
        sps[t] = sp[(size_t)s * Ev + t];
        __syncthreads();
        // Q[t] = dot(Wq row t, sp[s])  — iterate original group i4, slot (i4^tw)
        float acc = 0.f;
        const float* wr = Wq_s + (size_t)t * Ev;
        #pragma unroll
        for (int i4 = 0; i4 < 32; ++i4) {
            float4 w = *(const float4*)&wr[((i4 ^ tw) << 2)];
            // slot (i4^tw) holds original group ((i4^tw)^tw) = i4
            acc = fmaf(w.x, sps[i4 * 4 + 0], acc);
            acc = fmaf(w.y, sps[i4 * 4 + 1], acc);
            acc = fmaf(w.z, sps[i4 * 4 + 2], acc);
            acc = fmaf(w.w, sps[i4 * 4 + 3], acc);
        }
        Qs[t] = acc;
        __syncthreads();
        // qk[h][c4*4..] = 0.25 * sum_d Qs[h*16+d] * Wk[h*16+d][c]
        float4 a = make_float4(0.f, 0.f, 0.f, 0.f);
        #pragma unroll
        for (int d = 0; d < Dv; ++d) {
            int r = h * Dv + d;
            float q = Qs[r];
            float4 w = *(const float4*)&Wk_s[r * CKVv + ((c4 ^ (r & 15)) << 2)];
            a.x = fmaf(q, w.x, a.x);
            a.y = fmaf(q, w.y, a.y);
            a.z = fmaf(q, w.z, a.z);
            a.w = fmaf(q, w.w, a.w);
        }
        a.x *= 0.25f; a.y *= 0.25f; a.z *= 0.25f; a.w *= 0.25f;
        *(float4*)&g_qk[(size_t)s * QKD + h * CKVv + c4 * 4] = a;
        __syncthreads();
    }
}

// ---------------------------------------------------------------------------
// scan_kernel (launch 1): exclusive scan of g_cnt -> g_offs/g_cursor,
// then re-zero g_cnt (graph-replay invariant).
// ---------------------------------------------------------------------------
__global__ void scan_kernel() {
    __shared__ int wsum[32];
    int t = threadIdx.x, lane = t & 31, wid = t >> 5;
    int4 c = ((const int4*)g_cnt)[t];
    int sum = c.x + c.y + c.z + c.w;
    int v = sum;
    #pragma unroll
    for (int o = 1; o < 32; o <<= 1) {
        int u = __shfl_up_sync(0xffffffffu, v, o);
        if (lane >= o) v += u;
    }
    if (lane == 31) wsum[wid] = v;
    __syncthreads();
    if (wid == 0) {
        int w = wsum[lane];
        #pragma unroll
        for (int o = 1; o < 32; o <<= 1) {
            int u = __shfl_up_sync(0xffffffffu, w, o);
            if (lane >= o) w += u;
        }
        wsum[lane] = w;
    }
    __syncthreads();
    int base = (wid ? wsum[wid - 1] : 0) + v - sum;
    int o0 = base, o1 = o0 + c.x, o2 = o1 + c.y, o3 = o2 + c.z;
    int4 ov = make_int4(o0, o1, o2, o3);
    ((int4*)g_offs)[t]   = ov;
    ((int4*)g_cursor)[t] = ov;
    ((int4*)g_cnt)[t]    = make_int4(0, 0, 0, 0);   // reset for next replay
    if (t == 1023) g_offs[Sv] = o3 + c.w;
}

// ---------------------------------------------------------------------------
// scatter_kernel (launch 2): counting-sort scatter of point indices.
// ---------------------------------------------------------------------------
__global__ void scatter_kernel(const int* __restrict__ assign) {
    int tid = blockIdx.x * blockDim.x + threadIdx.x;
    if (tid < Nv) {
        int s = assign[tid];
        int pos = atomicAdd(&g_cursor[s], 1);
        g_order[pos] = tid;
    }
}

// ---------------------------------------------------------------------------
// seg_kernel (launch 3 — PROFILED): one block per segment, chunk = 128 points.
//  phase 1 (P<=64): 2 threads/point, 4 heads each — all 128 threads active.
//  phase 1 (P> 64): thread = point, 8 heads.
//  phase 2: thread (h,c4): A[h][c..] += w[h][p]*x[p][c..]
//  tail: stage Wv into smem (reuse x_s), ctx = (Wv.A[h])/den, residual + LN.
// ---------------------------------------------------------------------------
__global__ void __launch_bounds__(128)
seg_kernel(const float* __restrict__ xin, const float* __restrict__ sp,
           const float* __restrict__ lnw, const float* __restrict__ lnb,
           float* __restrict__ out, float* __restrict__ attn_out) {
    __shared__ float x_s[128 * 64];    // swizzled rows; reused for Wv in tail (32 KB)
    __shared__ float qk_s[QKD];        // 2 KB
    __shared__ float w_s[Hv * 128];    // [h][p] transposed (4 KB)
    __shared__ float ps_s[2 * 64];     // half-sums for P<=64 path
    __shared__ float A_s[Hv * CKVv];   // 2 KB
    __shared__ float den_s[Hv];
    __shared__ float red_s[4];

    int s = blockIdx.x, t = threadIdx.x;
    int lane = t & 31, warp = t >> 5;
    ((float4*)qk_s)[t] = ((const float4*)(g_qk + (size_t)s * QKD))[t];

    int start = g_offs[s], end = g_offs[s + 1];
    int h = t >> 4, c4 = t & 15;
    float4 A = make_float4(0.f, 0.f, 0.f, 0.f);
    float den = 0.f;
    __syncthreads();

    for (int base = start; base < end; base += 128) {
        int P = min(128, end - base);

        // stage x rows swizzled (coalesced 256 B per row)
        for (int idx = t; idx < P * 16; idx += 128) {
            int r = idx >> 4, cc = idx & 15;
            int p = g_order[base + r];
            float4 v = ((const float4*)xin)[(size_t)p * 16 + cc];
            *(float4*)&x_s[r * 64 + ((cc ^ (r & 15)) << 2)] = v;
        }
        __syncthreads();

        // ---- phase 1 ----
        if (P > 64) {
            if (t < P) {
                int sw = t & 15;
                float4 xr[16];
                #pragma unroll
                for (int i = 0; i < 16; ++i)
                    xr[i] = *(const float4*)&x_s[t * 64 + ((i ^ sw) << 2)];
                float ssum = 0.f;
                #pragma unroll
                for (int hd = 0; hd < Hv; ++hd) {
                    const float4* qv = (const float4*)(qk_s + hd * CKVv);
                    float sc = 0.f;
                    #pragma unroll
                    for (int i = 0; i < 16; ++i) {
                        float4 q = qv[i], x = xr[i];
                        sc = fmaf(q.x, x.x, sc);
                        sc = fmaf(q.y, x.y, sc);
                        sc = fmaf(q.z, x.z, sc);
                        sc = fmaf(q.w, x.w, sc);
                    }
                    ssum += sc;
                    w_s[hd * 128 + t] = __expf(sc);
                }
                attn_out[g_order[base + t]] = ssum * 0.125f;
            }
        } else {
            int p1 = t >> 1, half = t & 1;
            if (p1 < P) {
                int sw = p1 & 15;
                float4 xr[16];
                #pragma unroll
                for (int i = 0; i < 16; ++i)
                    xr[i] = *(const float4*)&x_s[p1 * 64 + ((i ^ sw) << 2)];
                float psum = 0.f;
                #pragma unroll
                for (int hh = 0; hh < 4; ++hh) {
                    int hd = half * 4 + hh;
                    const float4* qv = (const float4*)(qk_s + hd * CKVv);
                    float sc = 0.f;
                    #pragma unroll
                    for (int i = 0; i < 16; ++i) {
                        float4 q = qv[i], x = xr[i];
                        sc = fmaf(q.x, x.x, sc);
                        sc = fmaf(q.y, x.y, sc);
                        sc = fmaf(q.z, x.z, sc);
                        sc = fmaf(q.w, x.w, sc);
                    }
                    psum += sc;
                    w_s[hd * 128 + p1] = __expf(sc);
                }
                ps_s[half * 64 + p1] = psum;
            }
        }
        __syncthreads();

        if (P <= 64 && t < P)
            attn_out[g_order[base + t]] = (ps_s[t] + ps_s[64 + t]) * 0.125f;

        // ---- phase 2 ----
        int Pm = P & ~3;
        for (int p = 0; p < Pm; p += 4) {
            float4 wv = *(const float4*)&w_s[h * 128 + p];
            {
                int r = p;
                float4 xv = *(const float4*)&x_s[r * 64 + ((c4 ^ (r & 15)) << 2)];
                A.x = fmaf(wv.x, xv.x, A.x); A.y = fmaf(wv.x, xv.y, A.y);
                A.z = fmaf(wv.x, xv.z, A.z); A.w = fmaf(wv.x, xv.w, A.w);
            }
            {
                int r = p + 1;
                float4 xv = *(const float4*)&x_s[r * 64 + ((c4 ^ (r & 15)) << 2)];
                A.x = fmaf(wv.y, xv.x, A.x); A.y = fmaf(wv.y, xv.y, A.y);
                A.z = fmaf(wv.y, xv.z, A.z); A.w = fmaf(wv.y, xv.w, A.w);
            }
            {
                int r = p + 2;
                float4 xv = *(const float4*)&x_s[r * 64 + ((c4 ^ (r & 15)) << 2)];
                A.x = fmaf(wv.z, xv.x, A.x); A.y = fmaf(wv.z, xv.y, A.y);
                A.z = fmaf(wv.z, xv.z, A.z); A.w = fmaf(wv.z, xv.w, A.w);
            }
            {
                int r = p + 3;
                float4 xv = *(const float4*)&x_s[r * 64 + ((c4 ^ (r & 15)) << 2)];
                A.x = fmaf(wv.w, xv.x, A.x); A.y = fmaf(wv.w, xv.y, A.y);
                A.z = fmaf(wv.w, xv.z, A.z); A.w = fmaf(wv.w, xv.w, A.w);
            }
            if (c4 == 0) den += wv.x + wv.y + wv.z + wv.w;
        }
        for (int r = Pm; r < P; ++r) {
            float w = w_s[h * 128 + r];
            float4 xv = *(const float4*)&x_s[r * 64 + ((c4 ^ (r & 15)) << 2)];
            A.x = fmaf(w, xv.x, A.x); A.y = fmaf(w, xv.y, A.y);
            A.z = fmaf(w, xv.z, A.z); A.w = fmaf(w, xv.w, A.w);
            if (c4 == 0) den += w;
        }
        __syncthreads();
    }

    // ---- tail: Wv apply + residual + LayerNorm ----
    *(float4*)&A_s[h * CKVv + c4 * 4] = A;
    if (c4 == 0) den_s[h] = den;
    __syncthreads();

    // stage Wv into x_s (swizzled rows of 64 floats)
    for (int idx = t; idx < Ev * CKVv / 4; idx += 128) {
        int r = idx >> 4, cc = idx & 15;
        float4 v = ((const float4*)g_Wv)[idx];
        *(float4*)&x_s[r * 64 + ((cc ^ (r & 15)) << 2)] = v;
    }
    __syncthreads();

    // ctx for output dim t: dot(Wv row t, A_s[h]) / den
    int swt = t & 15;
    float acc = 0.f;
    const float* ah = A_s + h * CKVv;
    #pragma unroll
    for (int i = 0; i < 16; ++i) {
        float4 w = *(const float4*)&x_s[t * 64 + ((i ^ swt) << 2)];  // orig group i
        const float* a = ah + (i << 2);
        acc = fmaf(w.x, a[0], acc);
        acc = fmaf(w.y, a[1], acc);
        acc = fmaf(w.z, a[2], acc);
        acc = fmaf(w.w, a[3], acc);
    }
    float dd  = den_s[h];
    float ctx = dd > 0.f ? acc / dd : 0.f;
    float xval = sp[(size_t)s * Ev + t] + ctx;

    float v = xval;
    #pragma unroll
    for (int o = 16; o; o >>= 1) v += __shfl_xor_sync(0xffffffffu, v, o);
    if (lane == 0) red_s[warp] = v;
    __syncthreads();
    float mu = (red_s[0] + red_s[1] + red_s[2] + red_s[3]) * (1.f / Ev);
    float dv = xval - mu;
    float sq = dv * dv;
    #pragma unroll
    for (int o = 16; o; o >>= 1) sq += __shfl_xor_sync(0xffffffffu, sq, o);
    __syncthreads();
    if (lane == 0) red_s[warp] = sq;
    __syncthreads();
    float rstd = rsqrtf((red_s[0] + red_s[1] + red_s[2] + red_s[3]) * (1.f / Ev) + 1e-5f);
    out[(size_t)s * Ev + t] = dv * rstd * lnw[t] + lnb[t];
}

// ---------------------------------------------------------------------------
// Launch. Inputs: sp_feat, rawPoint_feat, point_assignments, Wq, Wkv, ln_w, ln_b
// Output: [updated_sp_feat (S*E) | attn_scores (N)] f32.
// Exactly 4 launches; seg_kernel is launch index 3 (the ncu-captured slot).
// ---------------------------------------------------------------------------
extern "C" void kernel_launch(void* const* d_in, const int* in_sizes, int n_in,
                              void* d_out, int out_size) {
    const float* sp     = (const float*)d_in[0];
    const float* xin    = (const float*)d_in[1];
    const int*   assign = (const int*)d_in[2];
    const float* Wq     = (const float*)d_in[3];
    const float* Wkv    = (const float*)d_in[4];
    const float* lnw    = (const float*)d_in[5];
    const float* lnb    = (const float*)d_in[6];
    float* out      = (float*)d_out;
    float* attn_out = out + (size_t)Sv * Ev;

    int pre_smem = (Ev * Ev + Ev * CKVv) * (int)sizeof(float);   // 96 KB
    cudaFuncSetAttribute(pre_kernel, cudaFuncAttributeMaxDynamicSharedMemorySize, pre_smem);
    pre_kernel<<<256, 128, pre_smem>>>(sp, Wq, Wkv, assign);

    scan_kernel<<<1, 1024>>>();
    scatter_kernel<<<Nv / 256, 256>>>(assign);
    seg_kernel<<<Sv, 128>>>(xin, sp, lnw, lnb, out, attn_out);
}

// round 7
// speedup vs baseline: 1.8696x; 1.0519x over previous
#include <cuda_runtime.h>

// Problem constants
#define Sv   4096
#define Nv   262144
#define Ev   128
#define Hv   8
#define Dv   16
#define CKVv 64
#define QKD  512      // Hv * CKVv

// Device scratch (g_cnt invariant: zero at kernel_launch entry; scan re-zeroes)
__device__ __align__(16) float g_Wv[Ev * CKVv];   // folded V weights [128][64]
__device__ __align__(16) float g_qk[Sv * QKD];    // per-segment folded query [S][8][64]
__device__ __align__(16) int g_cnt[Sv];
__device__ __align__(16) int g_offs[Sv + 4];
__device__ __align__(16) int g_cursor[Sv];
__device__ int g_order[Nv];

// ---------------------------------------------------------------------------
// pre_kernel (launch 0): histogram + fused Q/qk precompute + Wv fold.
// Swizzle: row r stores original float4-group c at slot (c ^ (r & M)); reads
// iterate the ORIGINAL index and address slot (i ^ (r & M)) -> conflict-free.
// ---------------------------------------------------------------------------
__global__ void __launch_bounds__(128)
pre_kernel(const float* __restrict__ sp, const float* __restrict__ Wq,
           const float* __restrict__ Wkv, const int* __restrict__ assign) {
    extern __shared__ float dyn[];
    float* Wq_s = dyn;                 // [128][128] swizzled
    float* Wk_s = dyn + Ev * Ev;       // [128][64]  swizzled (folded K)
    __shared__ float sps[Ev];
    __shared__ float Qs[Ev];

    int t = threadIdx.x;
    int gtid = blockIdx.x * 128 + t;

    // histogram
    for (int p = gtid; p < Nv; p += 256 * 128)
        atomicAdd(&g_cnt[assign[p]], 1);

    // stage Wq swizzled
    for (int idx = t; idx < Ev * Ev / 4; idx += 128) {
        int j = idx >> 5, i4 = idx & 31;
        float4 v = ((const float4*)Wq)[idx];
        *(float4*)&Wq_s[j * Ev + ((i4 ^ (j & 31)) << 2)] = v;
    }
    // fold + stage Wk (concat-duplication fold: cols c and c+64 summed)
    for (int idx = t; idx < Ev * CKVv / 4; idx += 128) {
        int r = idx >> 4, c4 = idx & 15;
        float4 a = *(const float4*)&Wkv[(size_t)r * 128 + c4 * 4];
        float4 b = *(const float4*)&Wkv[(size_t)r * 128 + 64 + c4 * 4];
        float4 v = make_float4(a.x + b.x, a.y + b.y, a.z + b.z, a.w + b.w);
        *(float4*)&Wk_s[r * CKVv + ((c4 ^ (r & 15)) << 2)] = v;
    }
    // block 0: fold Wv (rows 128..255) to global
    if (blockIdx.x == 0) {
        for (int idx = t; idx < Ev * CKVv / 4; idx += 128) {
            int r = idx >> 4, c4 = idx & 15;
            float4 a = *(const float4*)&Wkv[(size_t)(128 + r) * 128 + c4 * 4];
            float4 b = *(const float4*)&Wkv[(size_t)(128 + r) * 128 + 64 + c4 * 4];
            ((float4*)g_Wv)[idx] = make_float4(a.x + b.x, a.y + b.y, a.z + b.z, a.w + b.w);
        }
    }
    __syncthreads();

    int h = t >> 4, c4 = t & 15;
    int tw = t & 31;
    for (int s = blockIdx.x; s < Sv; s += gridDim.x) {
        sps[t] = sp[(size_t)s * Ev + t];
        __syncthreads();
        float acc = 0.f;
        const float* wr = Wq_s + (size_t)t * Ev;
        #pragma unroll
        for (int i4 = 0; i4 < 32; ++i4) {
            float4 w = *(const float4*)&wr[((i4 ^ tw) << 2)];  // slot (i4^tw) holds orig group i4
            acc = fmaf(w.x, sps[i4 * 4 + 0], acc);
            acc = fmaf(w.y, sps[i4 * 4 + 1], acc);
            acc = fmaf(w.z, sps[i4 * 4 + 2], acc);
            acc = fmaf(w.w, sps[i4 * 4 + 3], acc);
        }
        Qs[t] = acc;
        __syncthreads();
        float4 a = make_float4(0.f, 0.f, 0.f, 0.f);
        #pragma unroll
        for (int d = 0; d < Dv; ++d) {
            int r = h * Dv + d;
            float q = Qs[r];
            float4 w = *(const float4*)&Wk_s[r * CKVv + ((c4 ^ (r & 15)) << 2)];
            a.x = fmaf(q, w.x, a.x);
            a.y = fmaf(q, w.y, a.y);
            a.z = fmaf(q, w.z, a.z);
            a.w = fmaf(q, w.w, a.w);
        }
        a.x *= 0.25f; a.y *= 0.25f; a.z *= 0.25f; a.w *= 0.25f;
        *(float4*)&g_qk[(size_t)s * QKD + h * CKVv + c4 * 4] = a;
        __syncthreads();
    }
}

// ---------------------------------------------------------------------------
// scan_kernel (launch 1): exclusive scan of g_cnt; re-zeroes g_cnt.
// ---------------------------------------------------------------------------
__global__ void scan_kernel() {
    __shared__ int wsum[32];
    int t = threadIdx.x, lane = t & 31, wid = t >> 5;
    int4 c = ((const int4*)g_cnt)[t];
    int sum = c.x + c.y + c.z + c.w;
    int v = sum;
    #pragma unroll
    for (int o = 1; o < 32; o <<= 1) {
        int u = __shfl_up_sync(0xffffffffu, v, o);
        if (lane >= o) v += u;
    }
    if (lane == 31) wsum[wid] = v;
    __syncthreads();
    if (wid == 0) {
        int w = wsum[lane];
        #pragma unroll
        for (int o = 1; o < 32; o <<= 1) {
            int u = __shfl_up_sync(0xffffffffu, w, o);
            if (lane >= o) w += u;
        }
        wsum[lane] = w;
    }
    __syncthreads();
    int base = (wid ? wsum[wid - 1] : 0) + v - sum;
    int o0 = base, o1 = o0 + c.x, o2 = o1 + c.y, o3 = o2 + c.z;
    int4 ov = make_int4(o0, o1, o2, o3);
    ((int4*)g_offs)[t]   = ov;
    ((int4*)g_cursor)[t] = ov;
    ((int4*)g_cnt)[t]    = make_int4(0, 0, 0, 0);
    if (t == 1023) g_offs[Sv] = o3 + c.w;
}

// ---------------------------------------------------------------------------
// scatter_kernel (launch 2)
// ---------------------------------------------------------------------------
__global__ void scatter_kernel(const int* __restrict__ assign) {
    int tid = blockIdx.x * blockDim.x + threadIdx.x;
    if (tid < Nv) {
        int s = assign[tid];
        int pos = atomicAdd(&g_cursor[s], 1);
        g_order[pos] = tid;
    }
}

// ---------------------------------------------------------------------------
// seg_kernel (launch 3 — PROFILED): one block per segment, chunk = 128.
// Phase 1 STREAMS x (one float4 live) into 8/4 score accumulators instead of
// caching the row in 64 registers -> regs drop, occupancy 3 -> 5 blocks/SM.
// ---------------------------------------------------------------------------
__global__ void __launch_bounds__(128, 5)
seg_kernel(const float* __restrict__ xin, const float* __restrict__ sp,
           const float* __restrict__ lnw, const float* __restrict__ lnb,
           float* __restrict__ out, float* __restrict__ attn_out) {
    __shared__ float x_s[128 * 64];    // swizzled rows; reused for Wv in tail
    __shared__ float qk_s[QKD];
    __shared__ float w_s[Hv * 128];    // [h][p]
    __shared__ float ps_s[2 * 64];
    __shared__ float A_s[Hv * CKVv];
    __shared__ float den_s[Hv];
    __shared__ float red_s[4];

    int s = blockIdx.x, t = threadIdx.x;
    int lane = t & 31, warp = t >> 5;
    ((float4*)qk_s)[t] = ((const float4*)(g_qk + (size_t)s * QKD))[t];

    int start = g_offs[s], end = g_offs[s + 1];
    int h = t >> 4, c4 = t & 15;
    float4 A = make_float4(0.f, 0.f, 0.f, 0.f);
    float den = 0.f;
    __syncthreads();

    for (int base = start; base < end; base += 128) {
        int P = min(128, end - base);

        // stage x rows swizzled
        for (int idx = t; idx < P * 16; idx += 128) {
            int r = idx >> 4, cc = idx & 15;
            int p = g_order[base + r];
            float4 v = ((const float4*)xin)[(size_t)p * 16 + cc];
            *(float4*)&x_s[r * 64 + ((cc ^ (r & 15)) << 2)] = v;
        }
        __syncthreads();

        // ---- phase 1 (streaming x, multi-head accumulators) ----
        if (P > 64) {
            if (t < P) {
                int sw = t & 15;
                const float* xrow = x_s + t * 64;
                float sc0 = 0.f, sc1 = 0.f, sc2 = 0.f, sc3 = 0.f;
                float sc4 = 0.f, sc5 = 0.f, sc6 = 0.f, sc7 = 0.f;
                #pragma unroll
                for (int i = 0; i < 16; ++i) {
                    float4 x = *(const float4*)&xrow[((i ^ sw) << 2)];
                    float4 q;
                    q = *(const float4*)&qk_s[0 * 64 + (i << 2)];
                    sc0 = fmaf(q.x, x.x, sc0); sc0 = fmaf(q.y, x.y, sc0);
                    sc0 = fmaf(q.z, x.z, sc0); sc0 = fmaf(q.w, x.w, sc0);
                    q = *(const float4*)&qk_s[1 * 64 + (i << 2)];
                    sc1 = fmaf(q.x, x.x, sc1); sc1 = fmaf(q.y, x.y, sc1);
                    sc1 = fmaf(q.z, x.z, sc1); sc1 = fmaf(q.w, x.w, sc1);
                    q = *(const float4*)&qk_s[2 * 64 + (i << 2)];
                    sc2 = fmaf(q.x, x.x, sc2); sc2 = fmaf(q.y, x.y, sc2);
                    sc2 = fmaf(q.z, x.z, sc2); sc2 = fmaf(q.w, x.w, sc2);
                    q = *(const float4*)&qk_s[3 * 64 + (i << 2)];
                    sc3 = fmaf(q.x, x.x, sc3); sc3 = fmaf(q.y, x.y, sc3);
                    sc3 = fmaf(q.z, x.z, sc3); sc3 = fmaf(q.w, x.w, sc3);
                    q = *(const float4*)&qk_s[4 * 64 + (i << 2)];
                    sc4 = fmaf(q.x, x.x, sc4); sc4 = fmaf(q.y, x.y, sc4);
                    sc4 = fmaf(q.z, x.z, sc4); sc4 = fmaf(q.w, x.w, sc4);
                    q = *(const float4*)&qk_s[5 * 64 + (i << 2)];
                    sc5 = fmaf(q.x, x.x, sc5); sc5 = fmaf(q.y, x.y, sc5);
                    sc5 = fmaf(q.z, x.z, sc5); sc5 = fmaf(q.w, x.w, sc5);
                    q = *(const float4*)&qk_s[6 * 64 + (i << 2)];
                    sc6 = fmaf(q.x, x.x, sc6); sc6 = fmaf(q.y, x.y, sc6);
                    sc6 = fmaf(q.z, x.z, sc6); sc6 = fmaf(q.w, x.w, sc6);
                    q = *(const float4*)&qk_s[7 * 64 + (i << 2)];
                    sc7 = fmaf(q.x, x.x, sc7); sc7 = fmaf(q.y, x.y, sc7);
                    sc7 = fmaf(q.z, x.z, sc7); sc7 = fmaf(q.w, x.w, sc7);
                }
                w_s[0 * 128 + t] = __expf(sc0);
                w_s[1 * 128 + t] = __expf(sc1);
                w_s[2 * 128 + t] = __expf(sc2);
                w_s[3 * 128 + t] = __expf(sc3);
                w_s[4 * 128 + t] = __expf(sc4);
                w_s[5 * 128 + t] = __expf(sc5);
                w_s[6 * 128 + t] = __expf(sc6);
                w_s[7 * 128 + t] = __expf(sc7);
                float ssum = sc0 + sc1 + sc2 + sc3 + sc4 + sc5 + sc6 + sc7;
                attn_out[g_order[base + t]] = ssum * 0.125f;
            }
        } else {
            int p1 = t >> 1, half = t & 1;
            if (p1 < P) {
                int sw = p1 & 15;
                const float* xrow = x_s + p1 * 64;
                const float* qb = qk_s + half * 4 * 64;
                float sc0 = 0.f, sc1 = 0.f, sc2 = 0.f, sc3 = 0.f;
                #pragma unroll
                for (int i = 0; i < 16; ++i) {
                    float4 x = *(const float4*)&xrow[((i ^ sw) << 2)];
                    float4 q;
                    q = *(const float4*)&qb[0 * 64 + (i << 2)];
                    sc0 = fmaf(q.x, x.x, sc0); sc0 = fmaf(q.y, x.y, sc0);
                    sc0 = fmaf(q.z, x.z, sc0); sc0 = fmaf(q.w, x.w, sc0);
                    q = *(const float4*)&qb[1 * 64 + (i << 2)];
                    sc1 = fmaf(q.x, x.x, sc1); sc1 = fmaf(q.y, x.y, sc1);
                    sc1 = fmaf(q.z, x.z, sc1); sc1 = fmaf(q.w, x.w, sc1);
                    q = *(const float4*)&qb[2 * 64 + (i << 2)];
                    sc2 = fmaf(q.x, x.x, sc2); sc2 = fmaf(q.y, x.y, sc2);
                    sc2 = fmaf(q.z, x.z, sc2); sc2 = fmaf(q.w, x.w, sc2);
                    q = *(const float4*)&qb[3 * 64 + (i << 2)];
                    sc3 = fmaf(q.x, x.x, sc3); sc3 = fmaf(q.y, x.y, sc3);
                    sc3 = fmaf(q.z, x.z, sc3); sc3 = fmaf(q.w, x.w, sc3);
                }
                int hb = half * 4;
                w_s[(hb + 0) * 128 + p1] = __expf(sc0);
                w_s[(hb + 1) * 128 + p1] = __expf(sc1);
                w_s[(hb + 2) * 128 + p1] = __expf(sc2);
                w_s[(hb + 3) * 128 + p1] = __expf(sc3);
                ps_s[half * 64 + p1] = sc0 + sc1 + sc2 + sc3;
            }
        }
        __syncthreads();

        if (P <= 64 && t < P)
            attn_out[g_order[base + t]] = (ps_s[t] + ps_s[64 + t]) * 0.125f;

        // ---- phase 2 ----
        int Pm = P & ~3;
        for (int p = 0; p < Pm; p += 4) {
            float4 wv = *(const float4*)&w_s[h * 128 + p];
            {
                int r = p;
                float4 xv = *(const float4*)&x_s[r * 64 + ((c4 ^ (r & 15)) << 2)];
                A.x = fmaf(wv.x, xv.x, A.x); A.y = fmaf(wv.x, xv.y, A.y);
                A.z = fmaf(wv.x, xv.z, A.z); A.w = fmaf(wv.x, xv.w, A.w);
            }
            {
                int r = p + 1;
                float4 xv = *(const float4*)&x_s[r * 64 + ((c4 ^ (r & 15)) << 2)];
                A.x = fmaf(wv.y, xv.x, A.x); A.y = fmaf(wv.y, xv.y, A.y);
                A.z = fmaf(wv.y, xv.z, A.z); A.w = fmaf(wv.y, xv.w, A.w);
            }
            {
                int r = p + 2;
                float4 xv = *(const float4*)&x_s[r * 64 + ((c4 ^ (r & 15)) << 2)];
                A.x = fmaf(wv.z, xv.x, A.x); A.y = fmaf(wv.z, xv.y, A.y);
                A.z = fmaf(wv.z, xv.z, A.z); A.w = fmaf(wv.z, xv.w, A.w);
            }
            {
                int r = p + 3;
                float4 xv = *(const float4*)&x_s[r * 64 + ((c4 ^ (r & 15)) << 2)];
                A.x = fmaf(wv.w, xv.x, A.x); A.y = fmaf(wv.w, xv.y, A.y);
                A.z = fmaf(wv.w, xv.z, A.z); A.w = fmaf(wv.w, xv.w, A.w);
            }
            if (c4 == 0) den += wv.x + wv.y + wv.z + wv.w;
        }
        for (int r = Pm; r < P; ++r) {
            float w = w_s[h * 128 + r];
            float4 xv = *(const float4*)&x_s[r * 64 + ((c4 ^ (r & 15)) << 2)];
            A.x = fmaf(w, xv.x, A.x); A.y = fmaf(w, xv.y, A.y);
            A.z = fmaf(w, xv.z, A.z); A.w = fmaf(w, xv.w, A.w);
            if (c4 == 0) den += w;
        }
        __syncthreads();
    }

    // ---- tail: Wv apply + residual + LayerNorm ----
    *(float4*)&A_s[h * CKVv + c4 * 4] = A;
    if (c4 == 0) den_s[h] = den;
    __syncthreads();

    for (int idx = t; idx < Ev * CKVv / 4; idx += 128) {
        int r = idx >> 4, cc = idx & 15;
        float4 v = ((const float4*)g_Wv)[idx];
        *(float4*)&x_s[r * 64 + ((cc ^ (r & 15)) << 2)] = v;
    }
    __syncthreads();

    int swt = t & 15;
    float acc = 0.f;
    const float* ah = A_s + h * CKVv;
    #pragma unroll
    for (int i = 0; i < 16; ++i) {
        float4 w = *(const float4*)&x_s[t * 64 + ((i ^ swt) << 2)];  // orig group i
        const float* a = ah + (i << 2);
        acc = fmaf(w.x, a[0], acc);
        acc = fmaf(w.y, a[1], acc);
        acc = fmaf(w.z, a[2], acc);
        acc = fmaf(w.w, a[3], acc);
    }
    float dd  = den_s[h];
    float ctx = dd > 0.f ? acc / dd : 0.f;
    float xval = sp[(size_t)s * Ev + t] + ctx;

    float v = xval;
    #pragma unroll
    for (int o = 16; o; o >>= 1) v += __shfl_xor_sync(0xffffffffu, v, o);
    if (lane == 0) red_s[warp] = v;
    __syncthreads();
    float mu = (red_s[0] + red_s[1] + red_s[2] + red_s[3]) * (1.f / Ev);
    float dv = xval - mu;
    float sq = dv * dv;
    #pragma unroll
    for (int o = 16; o; o >>= 1) sq += __shfl_xor_sync(0xffffffffu, sq, o);
    __syncthreads();
    if (lane == 0) red_s[warp] = sq;
    __syncthreads();
    float rstd = rsqrtf((red_s[0] + red_s[1] + red_s[2] + red_s[3]) * (1.f / Ev) + 1e-5f);
    out[(size_t)s * Ev + t] = dv * rstd * lnw[t] + lnb[t];
}

// ---------------------------------------------------------------------------
// Launch: 4 launches; seg_kernel is launch index 3 (profiled slot).
// ---------------------------------------------------------------------------
extern "C" void kernel_launch(void* const* d_in, const int* in_sizes, int n_in,
                              void* d_out, int out_size) {
    const float* sp     = (const float*)d_in[0];
    const float* xin    = (const float*)d_in[1];
    const int*   assign = (const int*)d_in[2];
    const float* Wq     = (const float*)d_in[3];
    const float* Wkv    = (const float*)d_in[4];
    const float* lnw    = (const float*)d_in[5];
    const float* lnb    = (const float*)d_in[6];
    float* out      = (float*)d_out;
    float* attn_out = out + (size_t)Sv * Ev;

    int pre_smem = (Ev * Ev + Ev * CKVv) * (int)sizeof(float);   // 96 KB
    cudaFuncSetAttribute(pre_kernel, cudaFuncAttributeMaxDynamicSharedMemorySize, pre_smem);
    pre_kernel<<<256, 128, pre_smem>>>(sp, Wq, Wkv, assign);

    scan_kernel<<<1, 1024>>>();
    scatter_kernel<<<Nv / 256, 256>>>(assign);
    seg_kernel<<<Sv, 128>>>(xin, sp, lnw, lnb, out, attn_out);
}